// round 14
// baseline (speedup 1.0000x reference)
#include <cuda_runtime.h>
#include <cuda_fp16.h>
#include <cstdint>

#define N_NODES 100000
#define IN_DIM  256
#define OUT_DIM 64
#define N_SUP   2
#define N_EDGES 1600000
#define TOT_E   (N_SUP * N_EDGES)      // 3,200,000

#define SCAN_BLOCKS 100
#define CHUNK       1000               // SCAN_BLOCKS * CHUNK = 100000
#define CSR_THREADS 1024
#define N_TILES     782                // ceil(100000/128)
#define GEMM_CTAS   261                // one wave at 2 CTAs/SM; 3 tiles/CTA

// ---------------------------------------------------------------------------
// Scratch (static device allocations)
// ---------------------------------------------------------------------------
__device__ __half g_presup[(size_t)N_SUP * N_NODES * OUT_DIM];  // 25.6 MB (fp16)
__device__ uint2  g_Wfrag[N_SUP * 8 * 16 * 32];                 // 64 KB
__device__ int    g_counts[N_NODES + 1];                        // counts + grid-bar
__device__ int    g_rowstart[N_NODES + 1];
__device__ int    g_cursor[N_NODES];
__device__ int    g_partials[SCAN_BLOCKS];
__device__ uint2  g_payload[TOT_E];                             // 25.6 MB compact

__device__ __forceinline__ uint32_t pack_h2(__half lo, __half hi) {
    return ((uint32_t)__half_as_ushort(hi) << 16) | (uint32_t)__half_as_ushort(lo);
}

// ---------------------------------------------------------------------------
// W -> fp16 mma.sync B fragments: [s][ntile(8)][kstep(16)][lane(32)] -> uint2
// ---------------------------------------------------------------------------
__global__ void wfrag_kernel(const float* __restrict__ W) {
    int t = blockIdx.x * blockDim.x + threadIdx.x;   // 8192
    if (t >= N_SUP * 8 * 16 * 32) return;
    int lane  = t & 31;
    int kstep = (t >> 5) & 15;
    int ntile = (t >> 9) & 7;
    int s     = t >> 12;
    int n  = ntile * 8 + (lane >> 2);
    int k0 = kstep * 16 + (lane & 3) * 2;

    float v00 = W[((size_t)s * IN_DIM + k0 + 0) * OUT_DIM + n];
    float v01 = W[((size_t)s * IN_DIM + k0 + 1) * OUT_DIM + n];
    float v10 = W[((size_t)s * IN_DIM + k0 + 8) * OUT_DIM + n];
    float v11 = W[((size_t)s * IN_DIM + k0 + 9) * OUT_DIM + n];

    uint2 o;
    o.x = pack_h2(__float2half_rn(v00), __float2half_rn(v01));
    o.y = pack_h2(__float2half_rn(v10), __float2half_rn(v11));
    g_Wfrag[t] = o;
}

// ---------------------------------------------------------------------------
// Persistent GEMM via mma.sync.m16n8k16 fp16, single pass.
// Each CTA copies W fragments to smem ONCE, then loops over 128-row tiles.
// ---------------------------------------------------------------------------
__device__ __forceinline__ void mma16816(float d[4], const uint32_t a[4],
                                         uint32_t b0, uint32_t b1) {
    asm volatile(
        "mma.sync.aligned.m16n8k16.row.col.f32.f16.f16.f32 "
        "{%0,%1,%2,%3}, {%4,%5,%6,%7}, {%8,%9}, {%0,%1,%2,%3};"
        : "+f"(d[0]), "+f"(d[1]), "+f"(d[2]), "+f"(d[3])
        : "r"(a[0]), "r"(a[1]), "r"(a[2]), "r"(a[3]), "r"(b0), "r"(b1));
}

#define WFRAG_ELEMS (N_SUP * 8 * 16 * 32)
#define SMEM_SZ (WFRAG_ELEMS * 8)

__global__ __launch_bounds__(256)
void gemm_mma_kernel(const float* __restrict__ X, __half* __restrict__ PS) {
    extern __shared__ uint2 wfrag[];
    const int tid = threadIdx.x;

    {   // copy 64 KB as uint4 (once per CTA)
        const uint4* src = (const uint4*)g_Wfrag;
        uint4* dst = (uint4*)wfrag;
        #pragma unroll 4
        for (int i = tid; i < WFRAG_ELEMS / 2; i += 256) dst[i] = src[i];
    }
    __syncthreads();

    const int warp = tid >> 5;
    const int lane = tid & 31;
    const int rlo = lane >> 2;
    const int kc  = (lane & 3) * 2;

    for (int tile = blockIdx.x; tile < N_TILES; tile += GEMM_CTAS) {
        const long long rowBase = (long long)tile * 128 + warp * 16;
        if (rowBase >= N_NODES) continue;     // tail tile: only warps 0-1 active

        const float* x0 = X + (size_t)(rowBase + rlo) * IN_DIM + kc;

        float d[2][8][4];
        #pragma unroll
        for (int s = 0; s < 2; s++)
            #pragma unroll
            for (int n = 0; n < 8; n++)
                #pragma unroll
                for (int j = 0; j < 4; j++) d[s][n][j] = 0.f;

        #pragma unroll 4
        for (int ks = 0; ks < 16; ks++) {
            const float* xp = x0 + ks * 16;
            float2 v0 = *(const float2*)(xp);
            float2 v1 = *(const float2*)(xp + (size_t)8 * IN_DIM);
            float2 v2 = *(const float2*)(xp + 8);
            float2 v3 = *(const float2*)(xp + (size_t)8 * IN_DIM + 8);

            uint32_t ah[4];
            ah[0] = pack_h2(__float2half_rn(v0.x), __float2half_rn(v0.y));
            ah[1] = pack_h2(__float2half_rn(v1.x), __float2half_rn(v1.y));
            ah[2] = pack_h2(__float2half_rn(v2.x), __float2half_rn(v2.y));
            ah[3] = pack_h2(__float2half_rn(v3.x), __float2half_rn(v3.y));

            #pragma unroll
            for (int s = 0; s < 2; s++) {
                #pragma unroll
                for (int n = 0; n < 8; n++) {
                    uint2 b = wfrag[(((s * 8 + n) * 16) + ks) * 32 + lane];
                    mma16816(d[s][n], ah, b.x, b.y);
                }
            }
        }

        #pragma unroll
        for (int s = 0; s < 2; s++) {
            __half* base = PS + ((size_t)s * N_NODES + rowBase + rlo) * OUT_DIM + kc;
            #pragma unroll
            for (int n = 0; n < 8; n++) {
                __half2 lo = __halves2half2(__float2half_rn(d[s][n][0]),
                                            __float2half_rn(d[s][n][1]));
                __half2 hi = __halves2half2(__float2half_rn(d[s][n][2]),
                                            __float2half_rn(d[s][n][3]));
                *(__half2*)(base + n * 8)                       = lo;
                *(__half2*)(base + n * 8 + (size_t)8 * OUT_DIM) = hi;
            }
        }
    }
}

// ---------------------------------------------------------------------------
// Fused CSR build: hist -> scan -> scatter in ONE persistent kernel.
// 100 CTAs x 1024 threads (all resident); grid barriers via monotonic
// atomic counter (bar = counts[N_NODES], zeroed by the launch memset).
// ---------------------------------------------------------------------------
__device__ __forceinline__ void grid_bar(volatile int* bar, int target) {
    __syncthreads();
    if (threadIdx.x == 0) {
        __threadfence();
        atomicAdd((int*)bar, 1);
        while (*bar < target) { }
        __threadfence();
    }
    __syncthreads();
}

__global__ __launch_bounds__(CSR_THREADS)
void csr_fused_kernel(const float4* __restrict__ edge_val4,
                      const int4*   __restrict__ edge_src4,
                      const int4*   __restrict__ edge_dst4,
                      int* __restrict__ counts,     // [N_NODES], zeroed; +N_NODES = bar
                      int* __restrict__ rowstart,
                      int* __restrict__ cursor,
                      int* __restrict__ partials,
                      uint2* __restrict__ payload) {
    __shared__ int bufA[CSR_THREADS], bufB[CSR_THREADS];
    const int b = blockIdx.x, t = threadIdx.x;
    const int gthreads = SCAN_BLOCKS * CSR_THREADS;      // 102400
    const int gtid = b * CSR_THREADS + t;
    volatile int* bar = counts + N_NODES;

    // ---- Phase 1: histogram ----
    for (int i = gtid; i < TOT_E / 4; i += gthreads) {
        int4 d = edge_dst4[i];
        atomicAdd(&counts[d.x], 1);
        atomicAdd(&counts[d.y], 1);
        atomicAdd(&counts[d.z], 1);
        atomicAdd(&counts[d.w], 1);
    }
    grid_bar(bar, SCAN_BLOCKS);

    // ---- Phase 2: exclusive scan ----
    const int g = b * CHUNK + t;
    const int c = (t < CHUNK) ? counts[g] : 0;

    bufA[t] = c;
    __syncthreads();
    #pragma unroll
    for (int s = 512; s > 0; s >>= 1) {
        if (t < s) bufA[t] += bufA[t + s];
        __syncthreads();
    }
    if (t == 0) partials[b] = bufA[0];
    grid_bar(bar, 2 * SCAN_BLOCKS);

    int pre = (t < b) ? partials[t] : 0;
    __syncthreads();
    bufA[t] = pre;
    __syncthreads();
    #pragma unroll
    for (int s = 512; s > 0; s >>= 1) {
        if (t < s) bufA[t] += bufA[t + s];
        __syncthreads();
    }
    const int base = bufA[0];
    __syncthreads();

    bufA[t] = c;
    __syncthreads();
    int* in = bufA; int* out = bufB;
    for (int off = 1; off < CSR_THREADS; off <<= 1) {
        out[t] = in[t] + (t >= off ? in[t - off] : 0);
        __syncthreads();
        int* tmp = in; in = out; out = tmp;
    }
    if (t < CHUNK) {
        const int ex = base + (t ? in[t - 1] : 0);
        rowstart[g] = ex;
        cursor[g]   = ex;
    }
    if (b == SCAN_BLOCKS - 1 && t == CHUNK - 1)
        rowstart[N_NODES] = base + in[t];
    grid_bar(bar, 3 * SCAN_BLOCKS);

    // ---- Phase 3: scatter ----
    for (int i = gtid; i < TOT_E / 4; i += gthreads) {
        int4   dd = edge_dst4[i];
        int4   ss = edge_src4[i];
        float4 vv = edge_val4[i];
        const int supoff = (i >= N_EDGES / 4) ? N_NODES : 0;
        int p;
        p = atomicAdd(&cursor[dd.x], 1);
        payload[p] = make_uint2((unsigned)(ss.x + supoff), __float_as_uint(vv.x));
        p = atomicAdd(&cursor[dd.y], 1);
        payload[p] = make_uint2((unsigned)(ss.y + supoff), __float_as_uint(vv.y));
        p = atomicAdd(&cursor[dd.z], 1);
        payload[p] = make_uint2((unsigned)(ss.z + supoff), __float_as_uint(vv.z));
        p = atomicAdd(&cursor[dd.w], 1);
        payload[p] = make_uint2((unsigned)(ss.w + supoff), __float_as_uint(vv.w));
    }
}

// ---------------------------------------------------------------------------
// Gather (R10 winner): warp per node, payload shfl-broadcast, half-warp per
// row slice (uint2), 4 independent PS loads in flight. Streaming out store.
// ---------------------------------------------------------------------------
__global__ __launch_bounds__(256)
void gather_kernel(const __half* __restrict__ PS,
                   const int*   __restrict__ rowstart,
                   const uint2* __restrict__ payload,
                   float* __restrict__ out) {
    const int v = (blockIdx.x * 256 + threadIdx.x) >> 5;
    if (v >= N_NODES) return;
    const int lane = threadIdx.x & 31;
    const int half = lane >> 4;
    const int sl   = lane & 15;

    const int beg = rowstart[v];
    const int cnt = rowstart[v + 1] - beg;

    float4 a0 = make_float4(0.f, 0.f, 0.f, 0.f);
    float4 a1 = make_float4(0.f, 0.f, 0.f, 0.f);
    float4 a2 = make_float4(0.f, 0.f, 0.f, 0.f);
    float4 a3 = make_float4(0.f, 0.f, 0.f, 0.f);

    for (int base = 0; base < cnt; base += 32) {
        const int rem = cnt - base;
        uint2 p = make_uint2(0u, 0u);                 // idx 0, w 0 -> harmless
        if (lane < rem) p = payload[beg + base + lane];
        const int m = rem < 32 ? rem : 32;

        for (int e = 0; e < m; e += 8) {
            const uint32_t i0 = __shfl_sync(0xFFFFFFFFu, p.x, e + half);
            const uint32_t u0 = __shfl_sync(0xFFFFFFFFu, p.y, e + half);
            const uint32_t i1 = __shfl_sync(0xFFFFFFFFu, p.x, e + 2 + half);
            const uint32_t u1 = __shfl_sync(0xFFFFFFFFu, p.y, e + 2 + half);
            const uint32_t i2 = __shfl_sync(0xFFFFFFFFu, p.x, e + 4 + half);
            const uint32_t u2 = __shfl_sync(0xFFFFFFFFu, p.y, e + 4 + half);
            const uint32_t i3 = __shfl_sync(0xFFFFFFFFu, p.x, e + 6 + half);
            const uint32_t u3 = __shfl_sync(0xFFFFFFFFu, p.y, e + 6 + half);

            const uint2 q0 = *(const uint2*)(PS + (size_t)i0 * OUT_DIM + sl * 4);
            const uint2 q1 = *(const uint2*)(PS + (size_t)i1 * OUT_DIM + sl * 4);
            const uint2 q2 = *(const uint2*)(PS + (size_t)i2 * OUT_DIM + sl * 4);
            const uint2 q3 = *(const uint2*)(PS + (size_t)i3 * OUT_DIM + sl * 4);

            const float w0 = __uint_as_float(u0);
            const float w1 = __uint_as_float(u1);
            const float w2 = __uint_as_float(u2);
            const float w3 = __uint_as_float(u3);
            float2 m2;
            m2 = __half22float2(*(const __half2*)&q0.x); a0.x = fmaf(w0, m2.x, a0.x); a0.y = fmaf(w0, m2.y, a0.y);
            m2 = __half22float2(*(const __half2*)&q0.y); a0.z = fmaf(w0, m2.x, a0.z); a0.w = fmaf(w0, m2.y, a0.w);
            m2 = __half22float2(*(const __half2*)&q1.x); a1.x = fmaf(w1, m2.x, a1.x); a1.y = fmaf(w1, m2.y, a1.y);
            m2 = __half22float2(*(const __half2*)&q1.y); a1.z = fmaf(w1, m2.x, a1.z); a1.w = fmaf(w1, m2.y, a1.w);
            m2 = __half22float2(*(const __half2*)&q2.x); a2.x = fmaf(w2, m2.x, a2.x); a2.y = fmaf(w2, m2.y, a2.y);
            m2 = __half22float2(*(const __half2*)&q2.y); a2.z = fmaf(w2, m2.x, a2.z); a2.w = fmaf(w2, m2.y, a2.w);
            m2 = __half22float2(*(const __half2*)&q3.x); a3.x = fmaf(w3, m2.x, a3.x); a3.y = fmaf(w3, m2.y, a3.y);
            m2 = __half22float2(*(const __half2*)&q3.y); a3.z = fmaf(w3, m2.x, a3.z); a3.w = fmaf(w3, m2.y, a3.w);
        }
    }

    float4 acc = make_float4((a0.x + a1.x) + (a2.x + a3.x),
                             (a0.y + a1.y) + (a2.y + a3.y),
                             (a0.z + a1.z) + (a2.z + a3.z),
                             (a0.w + a1.w) + (a2.w + a3.w));

    acc.x += __shfl_xor_sync(0xFFFFFFFFu, acc.x, 16);
    acc.y += __shfl_xor_sync(0xFFFFFFFFu, acc.y, 16);
    acc.z += __shfl_xor_sync(0xFFFFFFFFu, acc.z, 16);
    acc.w += __shfl_xor_sync(0xFFFFFFFFu, acc.w, 16);

    if (half == 0) {
        float4 r = make_float4(fmaxf(acc.x, 0.f), fmaxf(acc.y, 0.f),
                               fmaxf(acc.z, 0.f), fmaxf(acc.w, 0.f));
        __stwt((float4*)(out + (size_t)v * OUT_DIM + sl * 4), r);
    }
}

// ---------------------------------------------------------------------------
// Launch: 5 graph nodes (memset, csr_fused) || (wfrag, gemm) -> gather
// ---------------------------------------------------------------------------
extern "C" void kernel_launch(void* const* d_in, const int* in_sizes, int n_in,
                              void* d_out, int out_size) {
    const float* x        = (const float*)d_in[0];
    const float* W        = (const float*)d_in[1];
    const float* edge_val = (const float*)d_in[2];
    const int*   edge_src = (const int*)  d_in[3];
    const int*   edge_dst = (const int*)  d_in[4];
    float* out = (float*)d_out;

    __half *PS; int *counts, *rowstart, *cursor, *partials; uint2 *payload;
    cudaGetSymbolAddress((void**)&PS,       g_presup);
    cudaGetSymbolAddress((void**)&counts,   g_counts);
    cudaGetSymbolAddress((void**)&rowstart, g_rowstart);
    cudaGetSymbolAddress((void**)&cursor,   g_cursor);
    cudaGetSymbolAddress((void**)&partials, g_partials);
    cudaGetSymbolAddress((void**)&payload,  g_payload);

    static cudaStream_t s1 = nullptr;
    static cudaEvent_t evFork = nullptr, evJoin = nullptr;
    if (!s1) {
        cudaFuncSetAttribute(gemm_mma_kernel,
                             cudaFuncAttributeMaxDynamicSharedMemorySize, SMEM_SZ);
        cudaStreamCreateWithFlags(&s1, cudaStreamNonBlocking);
        cudaEventCreateWithFlags(&evFork, cudaEventDisableTiming);
        cudaEventCreateWithFlags(&evJoin, cudaEventDisableTiming);
    }

    // fork
    cudaEventRecord(evFork, 0);
    cudaStreamWaitEvent(s1, evFork, 0);

    // --- Side stream: GEMM chain ---
    wfrag_kernel<<<(WFRAG_ELEMS + 255) / 256, 256, 0, s1>>>(W);
    gemm_mma_kernel<<<GEMM_CTAS, 256, SMEM_SZ, s1>>>(x, PS);

    // --- Default stream: fused CSR build ---
    cudaMemsetAsync(counts, 0, (N_NODES + 1) * sizeof(int), 0);   // counts + bar
    csr_fused_kernel<<<SCAN_BLOCKS, CSR_THREADS>>>(
        (const float4*)edge_val, (const int4*)edge_src, (const int4*)edge_dst,
        counts, rowstart, cursor, partials, payload);

    // join
    cudaEventRecord(evJoin, s1);
    cudaStreamWaitEvent(0, evJoin, 0);

    // --- Gather (fused spmm + relu) ---
    gather_kernel<<<(N_NODES * 32 + 255) / 256, 256>>>(PS, rowstart, payload, out);
}

// round 15
// speedup vs baseline: 1.1373x; 1.1373x over previous
#include <cuda_runtime.h>
#include <cuda_fp16.h>
#include <cstdint>

#define N_NODES 100000
#define IN_DIM  256
#define OUT_DIM 64
#define N_SUP   2
#define N_EDGES 1600000
#define TOT_E   (N_SUP * N_EDGES)      // 3,200,000

#define SCAN_BLOCKS 100
#define CHUNK       1000               // SCAN_BLOCKS * CHUNK = 100000 = N_NODES

// ---------------------------------------------------------------------------
// Scratch (static device allocations) — R10-winner layout
// ---------------------------------------------------------------------------
__device__ __half g_presup[(size_t)N_SUP * N_NODES * OUT_DIM];  // 25.6 MB (fp16)
__device__ uint2  g_Wfrag[N_SUP * 8 * 16 * 32];                 // 64 KB
__device__ int    g_counts[N_NODES];
__device__ int    g_rowstart[N_NODES + 1];
__device__ int    g_flags[SCAN_BLOCKS];
__device__ unsigned short g_rank[TOT_E];                        // 6.4 MB
__device__ uint2  g_payload[TOT_E];                             // 25.6 MB compact

__device__ __forceinline__ uint32_t pack_h2(__half lo, __half hi) {
    return ((uint32_t)__half_as_ushort(hi) << 16) | (uint32_t)__half_as_ushort(lo);
}

// ---------------------------------------------------------------------------
// W -> fp16 mma.sync B fragments: [s][ntile(8)][kstep(16)][lane(32)] -> uint2
// ---------------------------------------------------------------------------
__global__ void wfrag_kernel(const float* __restrict__ W) {
    int t = blockIdx.x * blockDim.x + threadIdx.x;   // 8192
    if (t >= N_SUP * 8 * 16 * 32) return;
    int lane  = t & 31;
    int kstep = (t >> 5) & 15;
    int ntile = (t >> 9) & 7;
    int s     = t >> 12;
    int n  = ntile * 8 + (lane >> 2);
    int k0 = kstep * 16 + (lane & 3) * 2;

    float v00 = W[((size_t)s * IN_DIM + k0 + 0) * OUT_DIM + n];
    float v01 = W[((size_t)s * IN_DIM + k0 + 1) * OUT_DIM + n];
    float v10 = W[((size_t)s * IN_DIM + k0 + 8) * OUT_DIM + n];
    float v11 = W[((size_t)s * IN_DIM + k0 + 9) * OUT_DIM + n];

    uint2 o;
    o.x = pack_h2(__float2half_rn(v00), __float2half_rn(v01));
    o.y = pack_h2(__float2half_rn(v10), __float2half_rn(v11));
    g_Wfrag[t] = o;
}

// ---------------------------------------------------------------------------
// GEMM via mma.sync.m16n8k16 fp16, single pass.
// ---------------------------------------------------------------------------
__device__ __forceinline__ void mma16816(float d[4], const uint32_t a[4],
                                         uint32_t b0, uint32_t b1) {
    asm volatile(
        "mma.sync.aligned.m16n8k16.row.col.f32.f16.f16.f32 "
        "{%0,%1,%2,%3}, {%4,%5,%6,%7}, {%8,%9}, {%0,%1,%2,%3};"
        : "+f"(d[0]), "+f"(d[1]), "+f"(d[2]), "+f"(d[3])
        : "r"(a[0]), "r"(a[1]), "r"(a[2]), "r"(a[3]), "r"(b0), "r"(b1));
}

#define WFRAG_ELEMS (N_SUP * 8 * 16 * 32)
#define SMEM_SZ (WFRAG_ELEMS * 8)

__global__ __launch_bounds__(256)
void gemm_mma_kernel(const float* __restrict__ X, __half* __restrict__ PS) {
    extern __shared__ uint2 wfrag[];
    const int tid = threadIdx.x;

    {   // copy 64 KB as uint4
        const uint4* src = (const uint4*)g_Wfrag;
        uint4* dst = (uint4*)wfrag;
        #pragma unroll 4
        for (int i = tid; i < WFRAG_ELEMS / 2; i += 256) dst[i] = src[i];
    }
    __syncthreads();

    const int warp = tid >> 5;
    const int lane = tid & 31;
    const long long wtile = (long long)blockIdx.x * 8 + warp;
    const long long rowBase = wtile * 16;
    if (rowBase >= N_NODES) return;

    const int rlo = lane >> 2;
    const int kc  = (lane & 3) * 2;
    const float* x0 = X + (size_t)(rowBase + rlo) * IN_DIM + kc;

    float d[2][8][4];
    #pragma unroll
    for (int s = 0; s < 2; s++)
        #pragma unroll
        for (int n = 0; n < 8; n++)
            #pragma unroll
            for (int j = 0; j < 4; j++) d[s][n][j] = 0.f;

    #pragma unroll 4
    for (int ks = 0; ks < 16; ks++) {
        const float* xp = x0 + ks * 16;
        float2 v0 = *(const float2*)(xp);
        float2 v1 = *(const float2*)(xp + (size_t)8 * IN_DIM);
        float2 v2 = *(const float2*)(xp + 8);
        float2 v3 = *(const float2*)(xp + (size_t)8 * IN_DIM + 8);

        uint32_t ah[4];
        ah[0] = pack_h2(__float2half_rn(v0.x), __float2half_rn(v0.y));
        ah[1] = pack_h2(__float2half_rn(v1.x), __float2half_rn(v1.y));
        ah[2] = pack_h2(__float2half_rn(v2.x), __float2half_rn(v2.y));
        ah[3] = pack_h2(__float2half_rn(v3.x), __float2half_rn(v3.y));

        #pragma unroll
        for (int s = 0; s < 2; s++) {
            #pragma unroll
            for (int n = 0; n < 8; n++) {
                uint2 b = wfrag[(((s * 8 + n) * 16) + ks) * 32 + lane];
                mma16816(d[s][n], ah, b.x, b.y);
            }
        }
    }

    #pragma unroll
    for (int s = 0; s < 2; s++) {
        __half* base = PS + ((size_t)s * N_NODES + rowBase + rlo) * OUT_DIM + kc;
        #pragma unroll
        for (int n = 0; n < 8; n++) {
            __half2 lo = __halves2half2(__float2half_rn(d[s][n][0]),
                                        __float2half_rn(d[s][n][1]));
            __half2 hi = __halves2half2(__float2half_rn(d[s][n][2]),
                                        __float2half_rn(d[s][n][3]));
            *(__half2*)(base + n * 8)                       = lo;
            *(__half2*)(base + n * 8 + (size_t)8 * OUT_DIM) = hi;
        }
    }
}

// ---------------------------------------------------------------------------
// Hist + rank
// ---------------------------------------------------------------------------
__global__ void hist_kernel(const int4* __restrict__ edge_dst4,
                            int* __restrict__ counts,
                            ushort4* __restrict__ rank4) {
    int i = blockIdx.x * blockDim.x + threadIdx.x;
    if (i < TOT_E / 4) {
        int4 d = edge_dst4[i];
        ushort4 r;
        r.x = (unsigned short)atomicAdd(&counts[d.x], 1);
        r.y = (unsigned short)atomicAdd(&counts[d.y], 1);
        r.z = (unsigned short)atomicAdd(&counts[d.z], 1);
        r.w = (unsigned short)atomicAdd(&counts[d.w], 1);
        rank4[i] = r;
    }
}

// ---------------------------------------------------------------------------
// Fused single-kernel exclusive scan (100 resident blocks, spin-lookback)
// ---------------------------------------------------------------------------
__global__ __launch_bounds__(1024)
void scan_fused_kernel(const int* __restrict__ counts,
                       int* __restrict__ rowstart,
                       volatile int* __restrict__ flags) {
    __shared__ int bufA[1024], bufB[1024];
    const int b = blockIdx.x, t = threadIdx.x;
    const int g = b * CHUNK + t;
    const int c = (t < CHUNK) ? counts[g] : 0;

    bufA[t] = c;
    __syncthreads();
    #pragma unroll
    for (int s = 512; s > 0; s >>= 1) {
        if (t < s) bufA[t] += bufA[t + s];
        __syncthreads();
    }
    if (t == 0) {
        __threadfence();
        atomicExch((int*)&flags[b], bufA[0] + 1);
    }
    __syncthreads();

    int pre = 0;
    if (t < b) {
        int v;
        do { v = flags[t]; } while (v == 0);
        pre = v - 1;
    }
    __syncthreads();
    bufA[t] = pre;
    __syncthreads();
    #pragma unroll
    for (int s = 512; s > 0; s >>= 1) {
        if (t < s) bufA[t] += bufA[t + s];
        __syncthreads();
    }
    const int base = bufA[0];
    __syncthreads();

    bufA[t] = c;
    __syncthreads();
    int* in = bufA; int* out = bufB;
    for (int off = 1; off < 1024; off <<= 1) {
        out[t] = in[t] + (t >= off ? in[t - off] : 0);
        __syncthreads();
        int* tmp = in; in = out; out = tmp;
    }
    if (t < CHUNK)
        rowstart[g] = base + (t ? in[t - 1] : 0);
    if (b == SCAN_BLOCKS - 1 && t == CHUNK - 1)
        rowstart[N_NODES] = base + in[t];
}

// ---------------------------------------------------------------------------
// Scatter (atomic-free): pos = rowstart[dst] + rank
// ---------------------------------------------------------------------------
__global__ void scatter_kernel(const float4* __restrict__ edge_val4,
                               const int4*   __restrict__ edge_src4,
                               const int4*   __restrict__ edge_dst4,
                               const ushort4* __restrict__ rank4,
                               const int* __restrict__ rowstart,
                               uint2* __restrict__ payload) {
    int i = blockIdx.x * blockDim.x + threadIdx.x;
    if (i >= TOT_E / 4) return;
    int4    dd = edge_dst4[i];
    int4    ss = edge_src4[i];
    float4  vv = edge_val4[i];
    ushort4 rr = rank4[i];
    const int supoff = (i >= N_EDGES / 4) ? N_NODES : 0;
    payload[rowstart[dd.x] + rr.x] = make_uint2((unsigned)(ss.x + supoff), __float_as_uint(vv.x));
    payload[rowstart[dd.y] + rr.y] = make_uint2((unsigned)(ss.y + supoff), __float_as_uint(vv.y));
    payload[rowstart[dd.z] + rr.z] = make_uint2((unsigned)(ss.z + supoff), __float_as_uint(vv.z));
    payload[rowstart[dd.w] + rr.w] = make_uint2((unsigned)(ss.w + supoff), __float_as_uint(vv.w));
}

// ---------------------------------------------------------------------------
// Gather (R10 loop, 2 accumulator chains, occupancy-boosted):
// warp per node, payload shfl-broadcast, half-warp per row slice (uint2),
// 4 PS loads batched before consumption. __launch_bounds__(256,6) -> ~75% occ.
// ---------------------------------------------------------------------------
__global__ __launch_bounds__(256, 6)
void gather_kernel(const __half* __restrict__ PS,
                   const int*   __restrict__ rowstart,
                   const uint2* __restrict__ payload,
                   float* __restrict__ out) {
    const int v = (blockIdx.x * 256 + threadIdx.x) >> 5;
    if (v >= N_NODES) return;
    const int lane = threadIdx.x & 31;
    const int half = lane >> 4;
    const int sl   = lane & 15;

    const int beg = rowstart[v];
    const int cnt = rowstart[v + 1] - beg;

    float4 a0 = make_float4(0.f, 0.f, 0.f, 0.f);
    float4 a1 = make_float4(0.f, 0.f, 0.f, 0.f);

    for (int base = 0; base < cnt; base += 32) {
        const int rem = cnt - base;
        uint2 p = make_uint2(0u, 0u);                 // idx 0, w 0 -> harmless
        if (lane < rem) p = payload[beg + base + lane];
        const int m = rem < 32 ? rem : 32;

        for (int e = 0; e < m; e += 8) {
            const uint32_t i0 = __shfl_sync(0xFFFFFFFFu, p.x, e + half);
            const uint32_t u0 = __shfl_sync(0xFFFFFFFFu, p.y, e + half);
            const uint32_t i1 = __shfl_sync(0xFFFFFFFFu, p.x, e + 2 + half);
            const uint32_t u1 = __shfl_sync(0xFFFFFFFFu, p.y, e + 2 + half);
            const uint32_t i2 = __shfl_sync(0xFFFFFFFFu, p.x, e + 4 + half);
            const uint32_t u2 = __shfl_sync(0xFFFFFFFFu, p.y, e + 4 + half);
            const uint32_t i3 = __shfl_sync(0xFFFFFFFFu, p.x, e + 6 + half);
            const uint32_t u3 = __shfl_sync(0xFFFFFFFFu, p.y, e + 6 + half);

            // 4 independent loads in flight before any consumption
            const uint2 q0 = *(const uint2*)(PS + (size_t)i0 * OUT_DIM + sl * 4);
            const uint2 q1 = *(const uint2*)(PS + (size_t)i1 * OUT_DIM + sl * 4);
            const uint2 q2 = *(const uint2*)(PS + (size_t)i2 * OUT_DIM + sl * 4);
            const uint2 q3 = *(const uint2*)(PS + (size_t)i3 * OUT_DIM + sl * 4);

            const float w0 = __uint_as_float(u0);
            const float w1 = __uint_as_float(u1);
            const float w2 = __uint_as_float(u2);
            const float w3 = __uint_as_float(u3);
            float2 m2;
            m2 = __half22float2(*(const __half2*)&q0.x); a0.x = fmaf(w0, m2.x, a0.x); a0.y = fmaf(w0, m2.y, a0.y);
            m2 = __half22float2(*(const __half2*)&q0.y); a0.z = fmaf(w0, m2.x, a0.z); a0.w = fmaf(w0, m2.y, a0.w);
            m2 = __half22float2(*(const __half2*)&q1.x); a1.x = fmaf(w1, m2.x, a1.x); a1.y = fmaf(w1, m2.y, a1.y);
            m2 = __half22float2(*(const __half2*)&q1.y); a1.z = fmaf(w1, m2.x, a1.z); a1.w = fmaf(w1, m2.y, a1.w);
            m2 = __half22float2(*(const __half2*)&q2.x); a0.x = fmaf(w2, m2.x, a0.x); a0.y = fmaf(w2, m2.y, a0.y);
            m2 = __half22float2(*(const __half2*)&q2.y); a0.z = fmaf(w2, m2.x, a0.z); a0.w = fmaf(w2, m2.y, a0.w);
            m2 = __half22float2(*(const __half2*)&q3.x); a1.x = fmaf(w3, m2.x, a1.x); a1.y = fmaf(w3, m2.y, a1.y);
            m2 = __half22float2(*(const __half2*)&q3.y); a1.z = fmaf(w3, m2.x, a1.z); a1.w = fmaf(w3, m2.y, a1.w);
        }
    }

    float4 acc = make_float4(a0.x + a1.x, a0.y + a1.y,
                             a0.z + a1.z, a0.w + a1.w);

    acc.x += __shfl_xor_sync(0xFFFFFFFFu, acc.x, 16);
    acc.y += __shfl_xor_sync(0xFFFFFFFFu, acc.y, 16);
    acc.z += __shfl_xor_sync(0xFFFFFFFFu, acc.z, 16);
    acc.w += __shfl_xor_sync(0xFFFFFFFFu, acc.w, 16);

    if (half == 0) {
        float4 r = make_float4(fmaxf(acc.x, 0.f), fmaxf(acc.y, 0.f),
                               fmaxf(acc.z, 0.f), fmaxf(acc.w, 0.f));
        *(float4*)(out + (size_t)v * OUT_DIM + sl * 4) = r;
    }
}

// ---------------------------------------------------------------------------
// Launch (R10 winner structure)
// ---------------------------------------------------------------------------
extern "C" void kernel_launch(void* const* d_in, const int* in_sizes, int n_in,
                              void* d_out, int out_size) {
    const float* x        = (const float*)d_in[0];
    const float* W        = (const float*)d_in[1];
    const float* edge_val = (const float*)d_in[2];
    const int*   edge_src = (const int*)  d_in[3];
    const int*   edge_dst = (const int*)  d_in[4];
    float* out = (float*)d_out;

    __half *PS; int *counts, *rowstart, *flags; unsigned short *rank; uint2 *payload;
    cudaGetSymbolAddress((void**)&PS,       g_presup);
    cudaGetSymbolAddress((void**)&counts,   g_counts);
    cudaGetSymbolAddress((void**)&rowstart, g_rowstart);
    cudaGetSymbolAddress((void**)&flags,    g_flags);
    cudaGetSymbolAddress((void**)&rank,     g_rank);
    cudaGetSymbolAddress((void**)&payload,  g_payload);

    static cudaStream_t s1 = nullptr;
    static cudaEvent_t evFork = nullptr, evJoin = nullptr;
    if (!s1) {
        cudaFuncSetAttribute(gemm_mma_kernel,
                             cudaFuncAttributeMaxDynamicSharedMemorySize, SMEM_SZ);
        cudaStreamCreateWithFlags(&s1, cudaStreamNonBlocking);
        cudaEventCreateWithFlags(&evFork, cudaEventDisableTiming);
        cudaEventCreateWithFlags(&evJoin, cudaEventDisableTiming);
    }

    // fork
    cudaEventRecord(evFork, 0);
    cudaStreamWaitEvent(s1, evFork, 0);

    // --- Side stream: GEMM chain ---
    wfrag_kernel<<<(WFRAG_ELEMS + 255) / 256, 256, 0, s1>>>(W);
    const int n_ctas = (N_NODES / 16 + 7) / 8;   // 782
    gemm_mma_kernel<<<n_ctas, 256, SMEM_SZ, s1>>>(x, PS);

    // --- Default stream: CSR chain ---
    cudaMemsetAsync(counts, 0, N_NODES * sizeof(int), 0);
    cudaMemsetAsync(flags, 0, SCAN_BLOCKS * sizeof(int), 0);
    hist_kernel<<<(TOT_E / 4 + 255) / 256, 256>>>(
        (const int4*)edge_dst, counts, (ushort4*)rank);
    scan_fused_kernel<<<SCAN_BLOCKS, 1024>>>(counts, rowstart, flags);
    scatter_kernel<<<(TOT_E / 4 + 255) / 256, 256>>>(
        (const float4*)edge_val, (const int4*)edge_src, (const int4*)edge_dst,
        (const ushort4*)rank, rowstart, payload);

    // join
    cudaEventRecord(evJoin, s1);
    cudaStreamWaitEvent(0, evJoin, 0);

    // --- Gather (fused spmm + relu) ---
    gather_kernel<<<(N_NODES * 32 + 255) / 256, 256>>>(PS, rowstart, payload, out);
}

// round 16
// speedup vs baseline: 1.1620x; 1.0217x over previous
#include <cuda_runtime.h>
#include <cuda_fp16.h>
#include <cstdint>

#define N_NODES 100000
#define IN_DIM  256
#define OUT_DIM 64
#define N_SUP   2
#define N_EDGES 1600000
#define TOT_E   (N_SUP * N_EDGES)      // 3,200,000

#define SCAN_BLOCKS 100
#define CHUNK       1000               // SCAN_BLOCKS * CHUNK = 100000 = N_NODES

// ---------------------------------------------------------------------------
// Scratch (static device allocations)
// ---------------------------------------------------------------------------
__device__ __half g_presup[(size_t)N_SUP * N_NODES * OUT_DIM];  // 25.6 MB (fp16)
__device__ uint2  g_Wfrag[N_SUP * 8 * 16 * 32];                 // 64 KB
__device__ int    g_counts[N_NODES + SCAN_BLOCKS];              // counts + flags (1 memset)
__device__ int    g_rowstart[N_NODES + 1];
__device__ unsigned short g_rank[TOT_E];                        // 6.4 MB
__device__ uint2  g_payload[TOT_E];                             // 25.6 MB compact

__device__ __forceinline__ uint32_t pack_h2(__half lo, __half hi) {
    return ((uint32_t)__half_as_ushort(hi) << 16) | (uint32_t)__half_as_ushort(lo);
}

// ---------------------------------------------------------------------------
// W -> fp16 mma.sync B fragments: [s][ntile(8)][kstep(16)][lane(32)] -> uint2
// ---------------------------------------------------------------------------
__global__ void wfrag_kernel(const float* __restrict__ W) {
    int t = blockIdx.x * blockDim.x + threadIdx.x;   // 8192
    if (t >= N_SUP * 8 * 16 * 32) return;
    int lane  = t & 31;
    int kstep = (t >> 5) & 15;
    int ntile = (t >> 9) & 7;
    int s     = t >> 12;
    int n  = ntile * 8 + (lane >> 2);
    int k0 = kstep * 16 + (lane & 3) * 2;

    float v00 = W[((size_t)s * IN_DIM + k0 + 0) * OUT_DIM + n];
    float v01 = W[((size_t)s * IN_DIM + k0 + 1) * OUT_DIM + n];
    float v10 = W[((size_t)s * IN_DIM + k0 + 8) * OUT_DIM + n];
    float v11 = W[((size_t)s * IN_DIM + k0 + 9) * OUT_DIM + n];

    uint2 o;
    o.x = pack_h2(__float2half_rn(v00), __float2half_rn(v01));
    o.y = pack_h2(__float2half_rn(v10), __float2half_rn(v11));
    g_Wfrag[t] = o;
}

// ---------------------------------------------------------------------------
// GEMM via mma.sync.m16n8k16 fp16, single pass.
// ---------------------------------------------------------------------------
__device__ __forceinline__ void mma16816(float d[4], const uint32_t a[4],
                                         uint32_t b0, uint32_t b1) {
    asm volatile(
        "mma.sync.aligned.m16n8k16.row.col.f32.f16.f16.f32 "
        "{%0,%1,%2,%3}, {%4,%5,%6,%7}, {%8,%9}, {%0,%1,%2,%3};"
        : "+f"(d[0]), "+f"(d[1]), "+f"(d[2]), "+f"(d[3])
        : "r"(a[0]), "r"(a[1]), "r"(a[2]), "r"(a[3]), "r"(b0), "r"(b1));
}

#define WFRAG_ELEMS (N_SUP * 8 * 16 * 32)
#define SMEM_SZ (WFRAG_ELEMS * 8)

__global__ __launch_bounds__(256)
void gemm_mma_kernel(const float* __restrict__ X, __half* __restrict__ PS) {
    extern __shared__ uint2 wfrag[];
    const int tid = threadIdx.x;

    {   // copy 64 KB as uint4
        const uint4* src = (const uint4*)g_Wfrag;
        uint4* dst = (uint4*)wfrag;
        #pragma unroll 4
        for (int i = tid; i < WFRAG_ELEMS / 2; i += 256) dst[i] = src[i];
    }
    __syncthreads();

    const int warp = tid >> 5;
    const int lane = tid & 31;
    const long long wtile = (long long)blockIdx.x * 8 + warp;
    const long long rowBase = wtile * 16;
    if (rowBase >= N_NODES) return;

    const int rlo = lane >> 2;
    const int kc  = (lane & 3) * 2;
    const float* x0 = X + (size_t)(rowBase + rlo) * IN_DIM + kc;

    float d[2][8][4];
    #pragma unroll
    for (int s = 0; s < 2; s++)
        #pragma unroll
        for (int n = 0; n < 8; n++)
            #pragma unroll
            for (int j = 0; j < 4; j++) d[s][n][j] = 0.f;

    #pragma unroll 4
    for (int ks = 0; ks < 16; ks++) {
        const float* xp = x0 + ks * 16;
        float2 v0 = *(const float2*)(xp);
        float2 v1 = *(const float2*)(xp + (size_t)8 * IN_DIM);
        float2 v2 = *(const float2*)(xp + 8);
        float2 v3 = *(const float2*)(xp + (size_t)8 * IN_DIM + 8);

        uint32_t ah[4];
        ah[0] = pack_h2(__float2half_rn(v0.x), __float2half_rn(v0.y));
        ah[1] = pack_h2(__float2half_rn(v1.x), __float2half_rn(v1.y));
        ah[2] = pack_h2(__float2half_rn(v2.x), __float2half_rn(v2.y));
        ah[3] = pack_h2(__float2half_rn(v3.x), __float2half_rn(v3.y));

        #pragma unroll
        for (int s = 0; s < 2; s++) {
            #pragma unroll
            for (int n = 0; n < 8; n++) {
                uint2 b = wfrag[(((s * 8 + n) * 16) + ks) * 32 + lane];
                mma16816(d[s][n], ah, b.x, b.y);
            }
        }
    }

    #pragma unroll
    for (int s = 0; s < 2; s++) {
        __half* base = PS + ((size_t)s * N_NODES + rowBase + rlo) * OUT_DIM + kc;
        #pragma unroll
        for (int n = 0; n < 8; n++) {
            __half2 lo = __halves2half2(__float2half_rn(d[s][n][0]),
                                        __float2half_rn(d[s][n][1]));
            __half2 hi = __halves2half2(__float2half_rn(d[s][n][2]),
                                        __float2half_rn(d[s][n][3]));
            *(__half2*)(base + n * 8)                       = lo;
            *(__half2*)(base + n * 8 + (size_t)8 * OUT_DIM) = hi;
        }
    }
}

// ---------------------------------------------------------------------------
// Hist + rank
// ---------------------------------------------------------------------------
__global__ void hist_kernel(const int4* __restrict__ edge_dst4,
                            int* __restrict__ counts,
                            ushort4* __restrict__ rank4) {
    int i = blockIdx.x * blockDim.x + threadIdx.x;
    if (i < TOT_E / 4) {
        int4 d = edge_dst4[i];
        ushort4 r;
        r.x = (unsigned short)atomicAdd(&counts[d.x], 1);
        r.y = (unsigned short)atomicAdd(&counts[d.y], 1);
        r.z = (unsigned short)atomicAdd(&counts[d.z], 1);
        r.w = (unsigned short)atomicAdd(&counts[d.w], 1);
        rank4[i] = r;
    }
}

// ---------------------------------------------------------------------------
// Fused single-kernel exclusive scan (100 resident blocks, spin-lookback)
// ---------------------------------------------------------------------------
__global__ __launch_bounds__(1024)
void scan_fused_kernel(const int* __restrict__ counts,
                       int* __restrict__ rowstart,
                       volatile int* __restrict__ flags) {
    __shared__ int bufA[1024], bufB[1024];
    const int b = blockIdx.x, t = threadIdx.x;
    const int g = b * CHUNK + t;
    const int c = (t < CHUNK) ? counts[g] : 0;

    bufA[t] = c;
    __syncthreads();
    #pragma unroll
    for (int s = 512; s > 0; s >>= 1) {
        if (t < s) bufA[t] += bufA[t + s];
        __syncthreads();
    }
    if (t == 0) {
        __threadfence();
        atomicExch((int*)&flags[b], bufA[0] + 1);
    }
    __syncthreads();

    int pre = 0;
    if (t < b) {
        int v;
        do { v = flags[t]; } while (v == 0);
        pre = v - 1;
    }
    __syncthreads();
    bufA[t] = pre;
    __syncthreads();
    #pragma unroll
    for (int s = 512; s > 0; s >>= 1) {
        if (t < s) bufA[t] += bufA[t + s];
        __syncthreads();
    }
    const int base = bufA[0];
    __syncthreads();

    bufA[t] = c;
    __syncthreads();
    int* in = bufA; int* out = bufB;
    for (int off = 1; off < 1024; off <<= 1) {
        out[t] = in[t] + (t >= off ? in[t - off] : 0);
        __syncthreads();
        int* tmp = in; in = out; out = tmp;
    }
    if (t < CHUNK)
        rowstart[g] = base + (t ? in[t - 1] : 0);
    if (b == SCAN_BLOCKS - 1 && t == CHUNK - 1)
        rowstart[N_NODES] = base + in[t];
}

// ---------------------------------------------------------------------------
// Scatter (atomic-free): pos = rowstart[dst] + rank
// ---------------------------------------------------------------------------
__global__ void scatter_kernel(const float4* __restrict__ edge_val4,
                               const int4*   __restrict__ edge_src4,
                               const int4*   __restrict__ edge_dst4,
                               const ushort4* __restrict__ rank4,
                               const int* __restrict__ rowstart,
                               uint2* __restrict__ payload) {
    int i = blockIdx.x * blockDim.x + threadIdx.x;
    if (i >= TOT_E / 4) return;
    int4    dd = edge_dst4[i];
    int4    ss = edge_src4[i];
    float4  vv = edge_val4[i];
    ushort4 rr = rank4[i];
    const int supoff = (i >= N_EDGES / 4) ? N_NODES : 0;
    payload[rowstart[dd.x] + rr.x] = make_uint2((unsigned)(ss.x + supoff), __float_as_uint(vv.x));
    payload[rowstart[dd.y] + rr.y] = make_uint2((unsigned)(ss.y + supoff), __float_as_uint(vv.y));
    payload[rowstart[dd.z] + rr.z] = make_uint2((unsigned)(ss.z + supoff), __float_as_uint(vv.z));
    payload[rowstart[dd.w] + rr.w] = make_uint2((unsigned)(ss.w + supoff), __float_as_uint(vv.w));
}

// ---------------------------------------------------------------------------
// Gather (R15 loop, occupancy pushed to 8 CTAs/SM via launch_bounds(256,8)):
// warp per node, payload shfl-broadcast, half-warp per row slice (uint2),
// 4 PS loads batched before consumption, 2 accumulator chains.
// ---------------------------------------------------------------------------
__global__ __launch_bounds__(256, 8)
void gather_kernel(const __half* __restrict__ PS,
                   const int*   __restrict__ rowstart,
                   const uint2* __restrict__ payload,
                   float* __restrict__ out) {
    const int v = (blockIdx.x * 256 + threadIdx.x) >> 5;
    if (v >= N_NODES) return;
    const int lane = threadIdx.x & 31;
    const int half = lane >> 4;
    const int sl   = lane & 15;

    const int beg = rowstart[v];
    const int cnt = rowstart[v + 1] - beg;

    float4 a0 = make_float4(0.f, 0.f, 0.f, 0.f);
    float4 a1 = make_float4(0.f, 0.f, 0.f, 0.f);

    for (int base = 0; base < cnt; base += 32) {
        const int rem = cnt - base;
        uint2 p = make_uint2(0u, 0u);                 // idx 0, w 0 -> harmless
        if (lane < rem) p = payload[beg + base + lane];
        const int m = rem < 32 ? rem : 32;

        for (int e = 0; e < m; e += 8) {
            const uint32_t i0 = __shfl_sync(0xFFFFFFFFu, p.x, e + half);
            const uint32_t u0 = __shfl_sync(0xFFFFFFFFu, p.y, e + half);
            const uint32_t i1 = __shfl_sync(0xFFFFFFFFu, p.x, e + 2 + half);
            const uint32_t u1 = __shfl_sync(0xFFFFFFFFu, p.y, e + 2 + half);
            const uint32_t i2 = __shfl_sync(0xFFFFFFFFu, p.x, e + 4 + half);
            const uint32_t u2 = __shfl_sync(0xFFFFFFFFu, p.y, e + 4 + half);
            const uint32_t i3 = __shfl_sync(0xFFFFFFFFu, p.x, e + 6 + half);
            const uint32_t u3 = __shfl_sync(0xFFFFFFFFu, p.y, e + 6 + half);

            // 4 independent loads in flight before any consumption
            const uint2 q0 = *(const uint2*)(PS + (size_t)i0 * OUT_DIM + sl * 4);
            const uint2 q1 = *(const uint2*)(PS + (size_t)i1 * OUT_DIM + sl * 4);
            const uint2 q2 = *(const uint2*)(PS + (size_t)i2 * OUT_DIM + sl * 4);
            const uint2 q3 = *(const uint2*)(PS + (size_t)i3 * OUT_DIM + sl * 4);

            const float w0 = __uint_as_float(u0);
            const float w1 = __uint_as_float(u1);
            const float w2 = __uint_as_float(u2);
            const float w3 = __uint_as_float(u3);
            float2 m2;
            m2 = __half22float2(*(const __half2*)&q0.x); a0.x = fmaf(w0, m2.x, a0.x); a0.y = fmaf(w0, m2.y, a0.y);
            m2 = __half22float2(*(const __half2*)&q0.y); a0.z = fmaf(w0, m2.x, a0.z); a0.w = fmaf(w0, m2.y, a0.w);
            m2 = __half22float2(*(const __half2*)&q1.x); a1.x = fmaf(w1, m2.x, a1.x); a1.y = fmaf(w1, m2.y, a1.y);
            m2 = __half22float2(*(const __half2*)&q1.y); a1.z = fmaf(w1, m2.x, a1.z); a1.w = fmaf(w1, m2.y, a1.w);
            m2 = __half22float2(*(const __half2*)&q2.x); a0.x = fmaf(w2, m2.x, a0.x); a0.y = fmaf(w2, m2.y, a0.y);
            m2 = __half22float2(*(const __half2*)&q2.y); a0.z = fmaf(w2, m2.x, a0.z); a0.w = fmaf(w2, m2.y, a0.w);
            m2 = __half22float2(*(const __half2*)&q3.x); a1.x = fmaf(w3, m2.x, a1.x); a1.y = fmaf(w3, m2.y, a1.y);
            m2 = __half22float2(*(const __half2*)&q3.y); a1.z = fmaf(w3, m2.x, a1.z); a1.w = fmaf(w3, m2.y, a1.w);
        }
    }

    float4 acc = make_float4(a0.x + a1.x, a0.y + a1.y,
                             a0.z + a1.z, a0.w + a1.w);

    acc.x += __shfl_xor_sync(0xFFFFFFFFu, acc.x, 16);
    acc.y += __shfl_xor_sync(0xFFFFFFFFu, acc.y, 16);
    acc.z += __shfl_xor_sync(0xFFFFFFFFu, acc.z, 16);
    acc.w += __shfl_xor_sync(0xFFFFFFFFu, acc.w, 16);

    if (half == 0) {
        float4 r = make_float4(fmaxf(acc.x, 0.f), fmaxf(acc.y, 0.f),
                               fmaxf(acc.z, 0.f), fmaxf(acc.w, 0.f));
        *(float4*)(out + (size_t)v * OUT_DIM + sl * 4) = r;
    }
}

// ---------------------------------------------------------------------------
// Launch
// ---------------------------------------------------------------------------
extern "C" void kernel_launch(void* const* d_in, const int* in_sizes, int n_in,
                              void* d_out, int out_size) {
    const float* x        = (const float*)d_in[0];
    const float* W        = (const float*)d_in[1];
    const float* edge_val = (const float*)d_in[2];
    const int*   edge_src = (const int*)  d_in[3];
    const int*   edge_dst = (const int*)  d_in[4];
    float* out = (float*)d_out;

    __half *PS; int *counts, *rowstart; unsigned short *rank; uint2 *payload;
    cudaGetSymbolAddress((void**)&PS,       g_presup);
    cudaGetSymbolAddress((void**)&counts,   g_counts);
    cudaGetSymbolAddress((void**)&rowstart, g_rowstart);
    cudaGetSymbolAddress((void**)&rank,     g_rank);
    cudaGetSymbolAddress((void**)&payload,  g_payload);
    int* flags = counts + N_NODES;

    static cudaStream_t s1 = nullptr;
    static cudaEvent_t evFork = nullptr, evJoin = nullptr;
    if (!s1) {
        cudaFuncSetAttribute(gemm_mma_kernel,
                             cudaFuncAttributeMaxDynamicSharedMemorySize, SMEM_SZ);
        cudaStreamCreateWithFlags(&s1, cudaStreamNonBlocking);
        cudaEventCreateWithFlags(&evFork, cudaEventDisableTiming);
        cudaEventCreateWithFlags(&evJoin, cudaEventDisableTiming);
    }

    // fork
    cudaEventRecord(evFork, 0);
    cudaStreamWaitEvent(s1, evFork, 0);

    // --- Side stream: GEMM chain ---
    wfrag_kernel<<<(WFRAG_ELEMS + 255) / 256, 256, 0, s1>>>(W);
    const int n_ctas = (N_NODES / 16 + 7) / 8;   // 782
    gemm_mma_kernel<<<n_ctas, 256, SMEM_SZ, s1>>>(x, PS);

    // --- Default stream: CSR chain ---
    cudaMemsetAsync(counts, 0, (N_NODES + SCAN_BLOCKS) * sizeof(int), 0);
    hist_kernel<<<(TOT_E / 4 + 255) / 256, 256>>>(
        (const int4*)edge_dst, counts, (ushort4*)rank);
    scan_fused_kernel<<<SCAN_BLOCKS, 1024>>>(counts, rowstart, flags);
    scatter_kernel<<<(TOT_E / 4 + 255) / 256, 256>>>(
        (const float4*)edge_val, (const int4*)edge_src, (const int4*)edge_dst,
        (const ushort4*)rank, rowstart, payload);

    // join
    cudaEventRecord(evJoin, s1);
    cudaStreamWaitEvent(0, evJoin, 0);

    // --- Gather (fused spmm + relu) ---
    gather_kernel<<<(N_NODES * 32 + 255) / 256, 256>>>(PS, rowstart, payload, out);
}

// round 17
// speedup vs baseline: 1.1646x; 1.0022x over previous
#include <cuda_runtime.h>
#include <cuda_fp16.h>
#include <cstdint>

#define N_NODES 100000
#define IN_DIM  256
#define OUT_DIM 64
#define N_SUP   2
#define N_EDGES 1600000
#define TOT_E   (N_SUP * N_EDGES)      // 3,200,000

#define SCAN_BLOCKS 100
#define CHUNK       1000               // SCAN_BLOCKS * CHUNK = 100000 = N_NODES

// ---------------------------------------------------------------------------
// Scratch (static device allocations)
// ---------------------------------------------------------------------------
__device__ __half g_presup[(size_t)N_SUP * N_NODES * OUT_DIM];  // 25.6 MB (fp16)
__device__ uint2  g_Wfrag[N_SUP * 8 * 16 * 32];                 // 64 KB
__device__ int    g_counts[N_NODES + SCAN_BLOCKS];              // counts + flags (1 memset)
__device__ int    g_rowstart[N_NODES + 1];
__device__ unsigned short g_rank[TOT_E];                        // 6.4 MB
__device__ uint2  g_payload[TOT_E];                             // 25.6 MB compact

__device__ __forceinline__ uint32_t pack_h2(__half lo, __half hi) {
    return ((uint32_t)__half_as_ushort(hi) << 16) | (uint32_t)__half_as_ushort(lo);
}

// ---------------------------------------------------------------------------
// W -> fp16 mma.sync B fragments: [s][ntile(8)][kstep(16)][lane(32)] -> uint2
// ---------------------------------------------------------------------------
__global__ void wfrag_kernel(const float* __restrict__ W) {
    int t = blockIdx.x * blockDim.x + threadIdx.x;   // 8192
    if (t >= N_SUP * 8 * 16 * 32) return;
    int lane  = t & 31;
    int kstep = (t >> 5) & 15;
    int ntile = (t >> 9) & 7;
    int s     = t >> 12;
    int n  = ntile * 8 + (lane >> 2);
    int k0 = kstep * 16 + (lane & 3) * 2;

    float v00 = W[((size_t)s * IN_DIM + k0 + 0) * OUT_DIM + n];
    float v01 = W[((size_t)s * IN_DIM + k0 + 1) * OUT_DIM + n];
    float v10 = W[((size_t)s * IN_DIM + k0 + 8) * OUT_DIM + n];
    float v11 = W[((size_t)s * IN_DIM + k0 + 9) * OUT_DIM + n];

    uint2 o;
    o.x = pack_h2(__float2half_rn(v00), __float2half_rn(v01));
    o.y = pack_h2(__float2half_rn(v10), __float2half_rn(v11));
    g_Wfrag[t] = o;
}

// ---------------------------------------------------------------------------
// GEMM via mma.sync.m16n8k16 fp16, single pass.
// ---------------------------------------------------------------------------
__device__ __forceinline__ void mma16816(float d[4], const uint32_t a[4],
                                         uint32_t b0, uint32_t b1) {
    asm volatile(
        "mma.sync.aligned.m16n8k16.row.col.f32.f16.f16.f32 "
        "{%0,%1,%2,%3}, {%4,%5,%6,%7}, {%8,%9}, {%0,%1,%2,%3};"
        : "+f"(d[0]), "+f"(d[1]), "+f"(d[2]), "+f"(d[3])
        : "r"(a[0]), "r"(a[1]), "r"(a[2]), "r"(a[3]), "r"(b0), "r"(b1));
}

#define WFRAG_ELEMS (N_SUP * 8 * 16 * 32)
#define SMEM_SZ (WFRAG_ELEMS * 8)

__global__ __launch_bounds__(256)
void gemm_mma_kernel(const float* __restrict__ X, __half* __restrict__ PS) {
    extern __shared__ uint2 wfrag[];
    const int tid = threadIdx.x;

    {   // copy 64 KB as uint4
        const uint4* src = (const uint4*)g_Wfrag;
        uint4* dst = (uint4*)wfrag;
        #pragma unroll 4
        for (int i = tid; i < WFRAG_ELEMS / 2; i += 256) dst[i] = src[i];
    }
    __syncthreads();

    const int warp = tid >> 5;
    const int lane = tid & 31;
    const long long wtile = (long long)blockIdx.x * 8 + warp;
    const long long rowBase = wtile * 16;
    if (rowBase >= N_NODES) return;

    const int rlo = lane >> 2;
    const int kc  = (lane & 3) * 2;
    const float* x0 = X + (size_t)(rowBase + rlo) * IN_DIM + kc;

    float d[2][8][4];
    #pragma unroll
    for (int s = 0; s < 2; s++)
        #pragma unroll
        for (int n = 0; n < 8; n++)
            #pragma unroll
            for (int j = 0; j < 4; j++) d[s][n][j] = 0.f;

    #pragma unroll 4
    for (int ks = 0; ks < 16; ks++) {
        const float* xp = x0 + ks * 16;
        float2 v0 = *(const float2*)(xp);
        float2 v1 = *(const float2*)(xp + (size_t)8 * IN_DIM);
        float2 v2 = *(const float2*)(xp + 8);
        float2 v3 = *(const float2*)(xp + (size_t)8 * IN_DIM + 8);

        uint32_t ah[4];
        ah[0] = pack_h2(__float2half_rn(v0.x), __float2half_rn(v0.y));
        ah[1] = pack_h2(__float2half_rn(v1.x), __float2half_rn(v1.y));
        ah[2] = pack_h2(__float2half_rn(v2.x), __float2half_rn(v2.y));
        ah[3] = pack_h2(__float2half_rn(v3.x), __float2half_rn(v3.y));

        #pragma unroll
        for (int s = 0; s < 2; s++) {
            #pragma unroll
            for (int n = 0; n < 8; n++) {
                uint2 b = wfrag[(((s * 8 + n) * 16) + ks) * 32 + lane];
                mma16816(d[s][n], ah, b.x, b.y);
            }
        }
    }

    #pragma unroll
    for (int s = 0; s < 2; s++) {
        __half* base = PS + ((size_t)s * N_NODES + rowBase + rlo) * OUT_DIM + kc;
        #pragma unroll
        for (int n = 0; n < 8; n++) {
            __half2 lo = __halves2half2(__float2half_rn(d[s][n][0]),
                                        __float2half_rn(d[s][n][1]));
            __half2 hi = __halves2half2(__float2half_rn(d[s][n][2]),
                                        __float2half_rn(d[s][n][3]));
            *(__half2*)(base + n * 8)                       = lo;
            *(__half2*)(base + n * 8 + (size_t)8 * OUT_DIM) = hi;
        }
    }
}

// ---------------------------------------------------------------------------
// Hist + rank
// ---------------------------------------------------------------------------
__global__ void hist_kernel(const int4* __restrict__ edge_dst4,
                            int* __restrict__ counts,
                            ushort4* __restrict__ rank4) {
    int i = blockIdx.x * blockDim.x + threadIdx.x;
    if (i < TOT_E / 4) {
        int4 d = edge_dst4[i];
        ushort4 r;
        r.x = (unsigned short)atomicAdd(&counts[d.x], 1);
        r.y = (unsigned short)atomicAdd(&counts[d.y], 1);
        r.z = (unsigned short)atomicAdd(&counts[d.z], 1);
        r.w = (unsigned short)atomicAdd(&counts[d.w], 1);
        rank4[i] = r;
    }
}

// ---------------------------------------------------------------------------
// Fused single-kernel exclusive scan (100 resident blocks, spin-lookback)
// ---------------------------------------------------------------------------
__global__ __launch_bounds__(1024)
void scan_fused_kernel(const int* __restrict__ counts,
                       int* __restrict__ rowstart,
                       volatile int* __restrict__ flags) {
    __shared__ int bufA[1024], bufB[1024];
    const int b = blockIdx.x, t = threadIdx.x;
    const int g = b * CHUNK + t;
    const int c = (t < CHUNK) ? counts[g] : 0;

    bufA[t] = c;
    __syncthreads();
    #pragma unroll
    for (int s = 512; s > 0; s >>= 1) {
        if (t < s) bufA[t] += bufA[t + s];
        __syncthreads();
    }
    if (t == 0) {
        __threadfence();
        atomicExch((int*)&flags[b], bufA[0] + 1);
    }
    __syncthreads();

    int pre = 0;
    if (t < b) {
        int v;
        do { v = flags[t]; } while (v == 0);
        pre = v - 1;
    }
    __syncthreads();
    bufA[t] = pre;
    __syncthreads();
    #pragma unroll
    for (int s = 512; s > 0; s >>= 1) {
        if (t < s) bufA[t] += bufA[t + s];
        __syncthreads();
    }
    const int base = bufA[0];
    __syncthreads();

    bufA[t] = c;
    __syncthreads();
    int* in = bufA; int* out = bufB;
    for (int off = 1; off < 1024; off <<= 1) {
        out[t] = in[t] + (t >= off ? in[t - off] : 0);
        __syncthreads();
        int* tmp = in; in = out; out = tmp;
    }
    if (t < CHUNK)
        rowstart[g] = base + (t ? in[t - 1] : 0);
    if (b == SCAN_BLOCKS - 1 && t == CHUNK - 1)
        rowstart[N_NODES] = base + in[t];
}

// ---------------------------------------------------------------------------
// Scatter (atomic-free): pos = rowstart[dst] + rank
// ---------------------------------------------------------------------------
__global__ void scatter_kernel(const float4* __restrict__ edge_val4,
                               const int4*   __restrict__ edge_src4,
                               const int4*   __restrict__ edge_dst4,
                               const ushort4* __restrict__ rank4,
                               const int* __restrict__ rowstart,
                               uint2* __restrict__ payload) {
    int i = blockIdx.x * blockDim.x + threadIdx.x;
    if (i >= TOT_E / 4) return;
    int4    dd = edge_dst4[i];
    int4    ss = edge_src4[i];
    float4  vv = edge_val4[i];
    ushort4 rr = rank4[i];
    const int supoff = (i >= N_EDGES / 4) ? N_NODES : 0;
    payload[rowstart[dd.x] + rr.x] = make_uint2((unsigned)(ss.x + supoff), __float_as_uint(vv.x));
    payload[rowstart[dd.y] + rr.y] = make_uint2((unsigned)(ss.y + supoff), __float_as_uint(vv.y));
    payload[rowstart[dd.z] + rr.z] = make_uint2((unsigned)(ss.z + supoff), __float_as_uint(vv.z));
    payload[rowstart[dd.w] + rr.w] = make_uint2((unsigned)(ss.w + supoff), __float_as_uint(vv.w));
}

// ---------------------------------------------------------------------------
// Gather v5: warp per node, payload staged in warp-private smem (LDS.64
// broadcast replaces 2 SHFLs per edge -> half the MIO ops). Half-warp per
// row slice (uint2), 4 PS loads batched, 2 accumulator chains, 8 CTAs/SM.
// ---------------------------------------------------------------------------
__global__ __launch_bounds__(256, 8)
void gather_kernel(const __half* __restrict__ PS,
                   const int*   __restrict__ rowstart,
                   const uint2* __restrict__ payload,
                   float* __restrict__ out) {
    __shared__ uint2 stage[8][32];
    const int v = (blockIdx.x * 256 + threadIdx.x) >> 5;
    if (v >= N_NODES) return;
    const int warp = (threadIdx.x >> 5);
    const int lane = threadIdx.x & 31;
    const int half = lane >> 4;
    const int sl   = lane & 15;

    const int beg = rowstart[v];
    const int cnt = rowstart[v + 1] - beg;

    float4 a0 = make_float4(0.f, 0.f, 0.f, 0.f);
    float4 a1 = make_float4(0.f, 0.f, 0.f, 0.f);

    for (int base = 0; base < cnt; base += 32) {
        const int rem = cnt - base;
        uint2 p = make_uint2(0u, 0u);                 // idx 0, w 0 -> harmless
        if (lane < rem) p = payload[beg + base + lane];
        stage[warp][lane] = p;
        __syncwarp();
        const int m = rem < 32 ? rem : 32;

        for (int e = 0; e < m; e += 8) {
            const uint2 t0 = stage[warp][e + half];
            const uint2 t1 = stage[warp][e + 2 + half];
            const uint2 t2 = stage[warp][e + 4 + half];
            const uint2 t3 = stage[warp][e + 6 + half];

            // 4 independent loads in flight before any consumption
            const uint2 q0 = *(const uint2*)(PS + (size_t)t0.x * OUT_DIM + sl * 4);
            const uint2 q1 = *(const uint2*)(PS + (size_t)t1.x * OUT_DIM + sl * 4);
            const uint2 q2 = *(const uint2*)(PS + (size_t)t2.x * OUT_DIM + sl * 4);
            const uint2 q3 = *(const uint2*)(PS + (size_t)t3.x * OUT_DIM + sl * 4);

            const float w0 = __uint_as_float(t0.y);
            const float w1 = __uint_as_float(t1.y);
            const float w2 = __uint_as_float(t2.y);
            const float w3 = __uint_as_float(t3.y);
            float2 m2;
            m2 = __half22float2(*(const __half2*)&q0.x); a0.x = fmaf(w0, m2.x, a0.x); a0.y = fmaf(w0, m2.y, a0.y);
            m2 = __half22float2(*(const __half2*)&q0.y); a0.z = fmaf(w0, m2.x, a0.z); a0.w = fmaf(w0, m2.y, a0.w);
            m2 = __half22float2(*(const __half2*)&q1.x); a1.x = fmaf(w1, m2.x, a1.x); a1.y = fmaf(w1, m2.y, a1.y);
            m2 = __half22float2(*(const __half2*)&q1.y); a1.z = fmaf(w1, m2.x, a1.z); a1.w = fmaf(w1, m2.y, a1.w);
            m2 = __half22float2(*(const __half2*)&q2.x); a0.x = fmaf(w2, m2.x, a0.x); a0.y = fmaf(w2, m2.y, a0.y);
            m2 = __half22float2(*(const __half2*)&q2.y); a0.z = fmaf(w2, m2.x, a0.z); a0.w = fmaf(w2, m2.y, a0.w);
            m2 = __half22float2(*(const __half2*)&q3.x); a1.x = fmaf(w3, m2.x, a1.x); a1.y = fmaf(w3, m2.y, a1.y);
            m2 = __half22float2(*(const __half2*)&q3.y); a1.z = fmaf(w3, m2.x, a1.z); a1.w = fmaf(w3, m2.y, a1.w);
        }
        __syncwarp();   // protect stage before next block overwrites
    }

    float4 acc = make_float4(a0.x + a1.x, a0.y + a1.y,
                             a0.z + a1.z, a0.w + a1.w);

    acc.x += __shfl_xor_sync(0xFFFFFFFFu, acc.x, 16);
    acc.y += __shfl_xor_sync(0xFFFFFFFFu, acc.y, 16);
    acc.z += __shfl_xor_sync(0xFFFFFFFFu, acc.z, 16);
    acc.w += __shfl_xor_sync(0xFFFFFFFFu, acc.w, 16);

    if (half == 0) {
        float4 r = make_float4(fmaxf(acc.x, 0.f), fmaxf(acc.y, 0.f),
                               fmaxf(acc.z, 0.f), fmaxf(acc.w, 0.f));
        *(float4*)(out + (size_t)v * OUT_DIM + sl * 4) = r;
    }
}

// ---------------------------------------------------------------------------
// Launch
// ---------------------------------------------------------------------------
extern "C" void kernel_launch(void* const* d_in, const int* in_sizes, int n_in,
                              void* d_out, int out_size) {
    const float* x        = (const float*)d_in[0];
    const float* W        = (const float*)d_in[1];
    const float* edge_val = (const float*)d_in[2];
    const int*   edge_src = (const int*)  d_in[3];
    const int*   edge_dst = (const int*)  d_in[4];
    float* out = (float*)d_out;

    __half *PS; int *counts, *rowstart; unsigned short *rank; uint2 *payload;
    cudaGetSymbolAddress((void**)&PS,       g_presup);
    cudaGetSymbolAddress((void**)&counts,   g_counts);
    cudaGetSymbolAddress((void**)&rowstart, g_rowstart);
    cudaGetSymbolAddress((void**)&rank,     g_rank);
    cudaGetSymbolAddress((void**)&payload,  g_payload);
    int* flags = counts + N_NODES;

    static cudaStream_t s1 = nullptr;
    static cudaEvent_t evFork = nullptr, evJoin = nullptr;
    if (!s1) {
        cudaFuncSetAttribute(gemm_mma_kernel,
                             cudaFuncAttributeMaxDynamicSharedMemorySize, SMEM_SZ);
        cudaStreamCreateWithFlags(&s1, cudaStreamNonBlocking);
        cudaEventCreateWithFlags(&evFork, cudaEventDisableTiming);
        cudaEventCreateWithFlags(&evJoin, cudaEventDisableTiming);
    }

    // fork
    cudaEventRecord(evFork, 0);
    cudaStreamWaitEvent(s1, evFork, 0);

    // --- Side stream: GEMM chain ---
    wfrag_kernel<<<(WFRAG_ELEMS + 255) / 256, 256, 0, s1>>>(W);
    const int n_ctas = (N_NODES / 16 + 7) / 8;   // 782
    gemm_mma_kernel<<<n_ctas, 256, SMEM_SZ, s1>>>(x, PS);

    // --- Default stream: CSR chain ---
    cudaMemsetAsync(counts, 0, (N_NODES + SCAN_BLOCKS) * sizeof(int), 0);
    hist_kernel<<<(TOT_E / 4 + 255) / 256, 256>>>(
        (const int4*)edge_dst, counts, (ushort4*)rank);
    scan_fused_kernel<<<SCAN_BLOCKS, 1024>>>(counts, rowstart, flags);
    scatter_kernel<<<(TOT_E / 4 + 255) / 256, 256>>>(
        (const float4*)edge_val, (const int4*)edge_src, (const int4*)edge_dst,
        (const ushort4*)rank, rowstart, payload);

    // join
    cudaEventRecord(evJoin, s1);
    cudaStreamWaitEvent(0, evJoin, 0);

    // --- Gather (fused spmm + relu) ---
    gather_kernel<<<(N_NODES * 32 + 255) / 256, 256>>>(PS, rowstart, payload, out);
}